// round 16
// baseline (speedup 1.0000x reference)
#include <cuda_runtime.h>

#define HWPX (1024*1024)
#define NB 8
#define NA 8
#define NK 16
#define NSEG 17
#define EPSV 1e-4f
#define PXV 2   // float4 tiles per thread (8 pixels)

// per-block smem constant layout (floats):
// [0,32)    : per-axis float4: {A0*dxi, A1*dxi, A2*dxi, m2}
// [32,64)   : per-axis float4: {pv0, pv1, pv2, 0}
// [64,336)  : tab[a][k] as float2 (dy, c02), 8*17*2 = 272 floats
#define CB_AP   0
#define CB_PV   32
#define CB_TAB  64
#define CB_SIZE (64 + NA*NSEG*2)   // 336 floats

__global__ __launch_bounds__(256, 4)
void spline_fused_kernel(const float* __restrict__ raw,
                        const float* __restrict__ ys,
                        const float* __restrict__ A,
                        float* __restrict__ out) {
    __shared__ __align__(16) float sc[CB_SIZE];
    const int b = blockIdx.y;
    const size_t base = (size_t)b * 3 * HWPX;
    const int tid = threadIdx.x;
    // two adjacent 256-wide float4 tiles per block
    const int v0 = blockIdx.x * (256 * PXV) + tid;

    // ---- issue the big independent global loads FIRST (latency overlaps prologue)
    float4 Rv[PXV], Gv[PXV], Bw[PXV];
    #pragma unroll
    for (int p = 0; p < PXV; p++) {
        const int v = v0 + p * 256;
        Rv[p] = ((const float4*)(raw + base          ))[v];
        Gv[p] = ((const float4*)(raw + base +   HWPX ))[v];
        Bw[p] = ((const float4*)(raw + base + 2*HWPX ))[v];
    }

    // ---- parallel prologue: redundant per-block, spread over ~170 threads ----
    const float* Ab = A + b * 3 * NA;

    if (tid < 24) {
        // pinv element (a,c):  pinv = A^T (A A^T)^-1
        const int a = tid / 3;
        const int c = tid % 3;
        float Am[3][NA];
        #pragma unroll
        for (int i = 0; i < 3; i++)
            #pragma unroll
            for (int j = 0; j < NA; j++)
                Am[i][j] = __ldg(Ab + i * NA + j);

        float M[3][3];
        #pragma unroll
        for (int i = 0; i < 3; i++)
            #pragma unroll
            for (int j = 0; j < 3; j++) {
                float s = 0.f;
                #pragma unroll
                for (int k = 0; k < NA; k++) s += Am[i][k] * Am[j][k];
                M[i][j] = s;
            }
        float c00 = M[1][1]*M[2][2] - M[1][2]*M[2][1];
        float c01 = M[1][2]*M[2][0] - M[1][0]*M[2][2];
        float c02 = M[1][0]*M[2][1] - M[1][1]*M[2][0];
        float det = M[0][0]*c00 + M[0][1]*c01 + M[0][2]*c02;
        float id  = 1.0f / det;
        float invc[3];
        if (c == 0)      { invc[0] = c00*id;
                           invc[1] = c01*id;
                           invc[2] = c02*id; }
        else if (c == 1) { invc[0] = (M[0][2]*M[2][1] - M[0][1]*M[2][2])*id;
                           invc[1] = (M[0][0]*M[2][2] - M[0][2]*M[2][0])*id;
                           invc[2] = (M[0][1]*M[2][0] - M[0][0]*M[2][1])*id; }
        else             { invc[0] = (M[0][1]*M[1][2] - M[0][2]*M[1][1])*id;
                           invc[1] = (M[0][2]*M[1][0] - M[0][0]*M[1][2])*id;
                           invc[2] = (M[0][0]*M[1][1] - M[0][1]*M[1][0])*id; }
        float s = 0.f;
        #pragma unroll
        for (int k = 0; k < 3; k++) s += Am[k][a] * invc[k];
        sc[CB_PV + a * 4 + c] = s;
    } else if (tid >= 32 && tid < 40) {
        const int a = tid - 32;
        float v0c = __ldg(Ab + 0 * NA + a);
        float v1c = __ldg(Ab + 1 * NA + a);
        float v2c = __ldg(Ab + 2 * NA + a);
        float mn = fminf(v0c,0.f) + fminf(v1c,0.f) + fminf(v2c,0.f);
        float mx = fmaxf(v0c,0.f) + fmaxf(v1c,0.f) + fmaxf(v2c,0.f);
        float dx  = (mx + EPSV - mn) / 17.0f;
        float dxi = 1.0f / dx;
        sc[CB_AP + a * 4 + 0] = v0c * dxi;
        sc[CB_AP + a * 4 + 1] = v1c * dxi;
        sc[CB_AP + a * 4 + 2] = v2c * dxi;
        sc[CB_AP + a * 4 + 3] = -mn * dxi;
    } else if (tid >= 56 && tid < 64) {
        sc[CB_PV + (tid - 56) * 4 + 3] = 0.f;   // pv padding
    } else if (tid >= 64 && tid < 64 + NA * NSEG) {
        const int idx = tid - 64;
        const int a = idx / NSEG;
        const int k = idx % NSEG;
        float v0c = __ldg(Ab + 0 * NA + a);
        float v1c = __ldg(Ab + 1 * NA + a);
        float v2c = __ldg(Ab + 2 * NA + a);
        float mn = fminf(v0c,0.f) + fminf(v1c,0.f) + fminf(v2c,0.f);
        float mx = fmaxf(v0c,0.f) + fmaxf(v1c,0.f) + fmaxf(v2c,0.f);
        const float* ysa = ys + (b * NA + a) * NK;
        float ylo = (k == 0)  ? mn : __ldg(ysa + k - 1);
        float yhi = (k == NK) ? mx : __ldg(ysa + k);
        float dy   = yhi - ylo;
        float c02v = yhi - (float)(k + 1) * dy;
        sc[CB_TAB + (a * NSEG + k) * 2 + 0] = dy;
        sc[CB_TAB + (a * NSEG + k) * 2 + 1] = c02v;
    }
    __syncthreads();

    // ---- main loop: axis-outer over 8 pixels (constants amortized 8x) ----
    const float4* sap  = (const float4*)(sc + CB_AP);
    const float4* spv  = (const float4*)(sc + CB_PV);
    const float2* stab = (const float2*)(sc + CB_TAB);

    float rr[8] = {Rv[0].x, Rv[0].y, Rv[0].z, Rv[0].w, Rv[1].x, Rv[1].y, Rv[1].z, Rv[1].w};
    float gg[8] = {Gv[0].x, Gv[0].y, Gv[0].z, Gv[0].w, Gv[1].x, Gv[1].y, Gv[1].z, Gv[1].w};
    float bb[8] = {Bw[0].x, Bw[0].y, Bw[0].z, Bw[0].w, Bw[1].x, Bw[1].y, Bw[1].z, Bw[1].w};

    float a0[8], a1[8], a2[8];
    #pragma unroll
    for (int q = 0; q < 8; q++) { a0[q] = 0.f; a1[q] = 0.f; a2[q] = 0.f; }

    #pragma unroll
    for (int a = 0; a < NA; a++) {
        const float4 ap = sap[a];
        const float4 pv = spv[a];
        const float2* atab = stab + a * NSEG;
        #pragma unroll
        for (int q = 0; q < 8; q++) {
            // u in [0,17) by construction (EPS margin >> roundoff); trunc handles -eps
            float u = fmaf(rr[q], ap.x, fmaf(gg[q], ap.y, fmaf(bb[q], ap.z, ap.w)));
            int   k = (int)u;
            float2 tc = atab[k];
            float est = fmaf(u, tc.x, tc.y);
            a0[q] = fmaf(est, pv.x, a0[q]);
            a1[q] = fmaf(est, pv.y, a1[q]);
            a2[q] = fmaf(est, pv.z, a2[q]);
        }
    }

    #pragma unroll
    for (int p = 0; p < PXV; p++) {
        const int v = v0 + p * 256;
        ((float4*)(out + base          ))[v] = make_float4(a0[p*4+0], a0[p*4+1], a0[p*4+2], a0[p*4+3]);
        ((float4*)(out + base +   HWPX ))[v] = make_float4(a1[p*4+0], a1[p*4+1], a1[p*4+2], a1[p*4+3]);
        ((float4*)(out + base + 2*HWPX ))[v] = make_float4(a2[p*4+0], a2[p*4+1], a2[p*4+2], a2[p*4+3]);
    }
}

extern "C" void kernel_launch(void* const* d_in, const int* in_sizes, int n_in,
                              void* d_out, int out_size) {
    const float* raw = (const float*)d_in[0];
    const float* ys  = (const float*)d_in[1];
    const float* A   = (const float*)d_in[2];
    float* out = (float*)d_out;

    dim3 grid(HWPX / (256 * 4 * PXV), NB);
    spline_fused_kernel<<<grid, 256>>>(raw, ys, A, out);
}

// round 17
// speedup vs baseline: 1.0228x; 1.0228x over previous
#include <cuda_runtime.h>

#define HWPX (1024*1024)
#define NB 8
#define NA 8
#define NK 16
#define NSEG 17
#define EPSV 1e-4f
#define MAGIC 12582912.0f   // 1.5 * 2^23
#define DELTA 1e-4f

// per-block smem constant layout (floats):
// [0,32)    : per-axis float4: {A0*dxi, A1*dxi, A2*dxi, m2 - 0.5 + DELTA}
// [32,96)   : per-axis 8 floats: {pv0,pv0, pv1,pv1, pv2,pv2, 0,0} (f32x2 duplicated)
// [96,368)  : tab[a][k] as float2 (dy, c02''), c02'' = yhi - (k+0.5+DELTA)*dy
#define CB_AP   0
#define CB_PV   32
#define CB_TAB  96
#define CB_SIZE (96 + NA*NSEG*2)   // 368 floats

typedef unsigned long long ull;

__device__ __forceinline__ ull pk2(float lo, float hi) {
    ull r; asm("mov.b64 %0, {%1, %2};" : "=l"(r) : "f"(lo), "f"(hi)); return r;
}
__device__ __forceinline__ void upk2(ull v, float& lo, float& hi) {
    asm("mov.b64 {%0, %1}, %2;" : "=f"(lo), "=f"(hi) : "l"(v));
}
__device__ __forceinline__ ull fma2(ull a, ull b, ull c) {
    ull r; asm("fma.rn.f32x2 %0, %1, %2, %3;" : "=l"(r) : "l"(a), "l"(b), "l"(c)); return r;
}

__global__ __launch_bounds__(256, 6)
void spline_fused_kernel(const float* __restrict__ raw,
                        const float* __restrict__ ys,
                        const float* __restrict__ A,
                        float* __restrict__ out) {
    __shared__ __align__(16) float sc[CB_SIZE];
    const int b = blockIdx.y;
    const size_t base = (size_t)b * 3 * HWPX;
    const int vidx = blockIdx.x * 256 + threadIdx.x;   // float4 index within plane

    // ---- issue the big independent global loads FIRST (latency overlaps prologue)
    float4 R  = ((const float4*)(raw + base          ))[vidx];
    float4 G  = ((const float4*)(raw + base +   HWPX ))[vidx];
    float4 Bv = ((const float4*)(raw + base + 2*HWPX ))[vidx];

    // ---- parallel prologue: redundant per-block, spread over ~170 threads ----
    const int t = threadIdx.x;
    const float* Ab = A + b * 3 * NA;

    if (t < 24) {
        // pinv element (a,c):  pinv = A^T (A A^T)^-1, stored duplicated for f32x2
        const int a = t / 3;
        const int c = t % 3;
        float Am[3][NA];
        #pragma unroll
        for (int i = 0; i < 3; i++)
            #pragma unroll
            for (int j = 0; j < NA; j++)
                Am[i][j] = __ldg(Ab + i * NA + j);

        float M[3][3];
        #pragma unroll
        for (int i = 0; i < 3; i++)
            #pragma unroll
            for (int j = 0; j < 3; j++) {
                float s = 0.f;
                #pragma unroll
                for (int k = 0; k < NA; k++) s += Am[i][k] * Am[j][k];
                M[i][j] = s;
            }
        float c00 = M[1][1]*M[2][2] - M[1][2]*M[2][1];
        float c01 = M[1][2]*M[2][0] - M[1][0]*M[2][2];
        float c02 = M[1][0]*M[2][1] - M[1][1]*M[2][0];
        float det = M[0][0]*c00 + M[0][1]*c01 + M[0][2]*c02;
        float id  = 1.0f / det;
        float invc[3];
        if (c == 0)      { invc[0] = c00*id;
                           invc[1] = c01*id;
                           invc[2] = c02*id; }
        else if (c == 1) { invc[0] = (M[0][2]*M[2][1] - M[0][1]*M[2][2])*id;
                           invc[1] = (M[0][0]*M[2][2] - M[0][2]*M[2][0])*id;
                           invc[2] = (M[0][1]*M[2][0] - M[0][0]*M[2][1])*id; }
        else             { invc[0] = (M[0][1]*M[1][2] - M[0][2]*M[1][1])*id;
                           invc[1] = (M[0][2]*M[1][0] - M[0][0]*M[1][2])*id;
                           invc[2] = (M[0][0]*M[1][1] - M[0][1]*M[1][0])*id; }
        float s = 0.f;
        #pragma unroll
        for (int k = 0; k < 3; k++) s += Am[k][a] * invc[k];
        sc[CB_PV + a * 8 + c * 2 + 0] = s;
        sc[CB_PV + a * 8 + c * 2 + 1] = s;
    } else if (t >= 32 && t < 40) {
        const int a = t - 32;
        float v0 = __ldg(Ab + 0 * NA + a);
        float v1 = __ldg(Ab + 1 * NA + a);
        float v2 = __ldg(Ab + 2 * NA + a);
        float mn = fminf(v0,0.f) + fminf(v1,0.f) + fminf(v2,0.f);
        float mx = fmaxf(v0,0.f) + fmaxf(v1,0.f) + fmaxf(v2,0.f);
        float dx  = (mx + EPSV - mn) / 17.0f;
        float dxi = 1.0f / dx;
        sc[CB_AP + a * 4 + 0] = v0 * dxi;
        sc[CB_AP + a * 4 + 1] = v1 * dxi;
        sc[CB_AP + a * 4 + 2] = v2 * dxi;
        sc[CB_AP + a * 4 + 3] = -mn * dxi - 0.5f + DELTA;   // u' = u - 0.5 + DELTA
    } else if (t >= 56 && t < 64) {
        sc[CB_PV + (t - 56) * 8 + 6] = 0.f;   // pv padding
        sc[CB_PV + (t - 56) * 8 + 7] = 0.f;
    } else if (t >= 64 && t < 64 + NA * NSEG) {
        const int idx = t - 64;
        const int a = idx / NSEG;
        const int k = idx % NSEG;
        float v0 = __ldg(Ab + 0 * NA + a);
        float v1 = __ldg(Ab + 1 * NA + a);
        float v2 = __ldg(Ab + 2 * NA + a);
        float mn = fminf(v0,0.f) + fminf(v1,0.f) + fminf(v2,0.f);
        float mx = fmaxf(v0,0.f) + fmaxf(v1,0.f) + fmaxf(v2,0.f);
        const float* ysa = ys + (b * NA + a) * NK;
        float ylo = (k == 0)  ? mn : __ldg(ysa + k - 1);
        float yhi = (k == NK) ? mx : __ldg(ysa + k);
        float dy   = yhi - ylo;
        // est = fma(u', dy, c02'') with u' = u - (0.5 - DELTA)
        float c02v = yhi - ((float)k + 0.5f + DELTA) * dy;
        sc[CB_TAB + (a * NSEG + k) * 2 + 0] = dy;
        sc[CB_TAB + (a * NSEG + k) * 2 + 1] = c02v;
    }
    __syncthreads();

    // ---- main loop ----
    const float4* sap  = (const float4*)(sc + CB_AP);
    const float2* stab = (const float2*)(sc + CB_TAB);

    float rr[4] = {R.x,  R.y,  R.z,  R.w};
    float gg[4] = {G.x,  G.y,  G.z,  G.w};
    float bb[4] = {Bv.x, Bv.y, Bv.z, Bv.w};

    ull acc0_01 = 0ULL, acc0_23 = 0ULL;
    ull acc1_01 = 0ULL, acc1_23 = 0ULL;
    ull acc2_01 = 0ULL, acc2_23 = 0ULL;

    #pragma unroll
    for (int a = 0; a < NA; a++) {
        const float4 ap = sap[a];
        const ull* pvp = (const ull*)(sc + CB_PV + a * 8);
        const ull PV0 = pvp[0];
        const ull PV1 = pvp[1];
        const ull PV2 = pvp[2];
        const float2* atab = stab + a * NSEG;

        float est[4];
        #pragma unroll
        for (int q = 0; q < 4; q++) {
            // u' = u - 0.5 + DELTA; round(u') == floor(u) (knot-continuity absorbs ties)
            float u = fmaf(rr[q], ap.x, fmaf(gg[q], ap.y, fmaf(bb[q], ap.z, ap.w)));
            int   k = __float_as_int(u + MAGIC) & 31;   // in [0,16] by range proof
            float2 tc = atab[k];
            est[q] = fmaf(u, tc.x, tc.y);
        }
        ull e01 = pk2(est[0], est[1]);
        ull e23 = pk2(est[2], est[3]);
        acc0_01 = fma2(e01, PV0, acc0_01);
        acc0_23 = fma2(e23, PV0, acc0_23);
        acc1_01 = fma2(e01, PV1, acc1_01);
        acc1_23 = fma2(e23, PV1, acc1_23);
        acc2_01 = fma2(e01, PV2, acc2_01);
        acc2_23 = fma2(e23, PV2, acc2_23);
    }

    float o0, o1, o2, o3;
    upk2(acc0_01, o0, o1); upk2(acc0_23, o2, o3);
    ((float4*)(out + base          ))[vidx] = make_float4(o0, o1, o2, o3);
    upk2(acc1_01, o0, o1); upk2(acc1_23, o2, o3);
    ((float4*)(out + base +   HWPX ))[vidx] = make_float4(o0, o1, o2, o3);
    upk2(acc2_01, o0, o1); upk2(acc2_23, o2, o3);
    ((float4*)(out + base + 2*HWPX ))[vidx] = make_float4(o0, o1, o2, o3);
}

extern "C" void kernel_launch(void* const* d_in, const int* in_sizes, int n_in,
                              void* d_out, int out_size) {
    const float* raw = (const float*)d_in[0];
    const float* ys  = (const float*)d_in[1];
    const float* A   = (const float*)d_in[2];
    float* out = (float*)d_out;

    dim3 grid(HWPX / (256 * 4), NB);
    spline_fused_kernel<<<grid, 256>>>(raw, ys, A, out);
}